// round 1
// baseline (speedup 1.0000x reference)
#include <cuda_runtime.h>

// Causal linear attention (elu+1 feature map), chunked-parallel formulation.
// Shapes fixed by the problem: [B=8, L=2048, H=16, D=64], M=64.
//
//   Phase 1: per (pair, chunk): P_c = phi(K_c)^T V_c  (64x64), ksum_c[d]
//   Phase 2: per pair: exclusive prefix-sum over the 16 chunks (in place)
//   Phase 3: per (pair, chunk): A = tril(phi(Q)phi(K)^T);
//            out = (A V + phi(Q) S_prev) / (rowsum(A) + phi(Q).kcum_prev + eps)

#define BB 8
#define LL 2048
#define HH 16
#define DD 64
#define MM 64
#define CC 128
#define NC (LL/CC)      // 16
#define NP (BB*HH)      // 128
#define EPSV 1e-6f

// Scratch: 128 pairs * 16 chunks * 64*64 floats = 33.5 MB
__device__ float g_P[(size_t)NP * NC * DD * MM];
__device__ float g_ks[NP * NC * DD];

__device__ __forceinline__ float phi(float x) {
    // elu(x) + 1 : x>0 -> x+1 ; x<=0 -> exp(x)
    return x > 0.f ? x + 1.f : __expf(x);
}

// ---------------------------------------------------------------------------
// Kernel 1: per-chunk K^T V and ksum. blocks = NP*NC, 256 threads.
// smem: Ks[128][64] + Vs[128][64] = 64 KB dynamic.
// ---------------------------------------------------------------------------
__global__ void k1_chunk_kv(const float* __restrict__ kin,
                            const float* __restrict__ vin) {
    extern __shared__ float sm[];
    float* Ks = sm;             // [CC][DD]
    float* Vs = sm + CC * DD;   // [CC][DD]

    int blk = blockIdx.x;
    int p = blk >> 4, c = blk & (NC - 1);
    int n = p >> 4, h = p & 15;
    int tid = threadIdx.x;

    size_t base = ((size_t)(n * LL + c * CC) * HH + h) * DD;

    for (int e = tid; e < CC * DD / 4; e += 256) {
        int j = e >> 4, dd = e & 15;
        size_t g = base + (size_t)j * HH * DD + dd * 4;
        float4 kv = *(const float4*)(kin + g);
        kv.x = phi(kv.x); kv.y = phi(kv.y); kv.z = phi(kv.z); kv.w = phi(kv.w);
        *(float4*)(Ks + j * DD + dd * 4) = kv;
        *(float4*)(Vs + j * DD + dd * 4) = *(const float4*)(vin + g);
    }
    __syncthreads();

    int ty = tid >> 4, tx = tid & 15;   // d-tile, m-tile (interleaved by 16)
    float acc[4][4] = {};
    for (int j = 0; j < CC; j++) {
        float kr[4], vr[4];
#pragma unroll
        for (int r = 0; r < 4; r++) {
            kr[r] = Ks[j * DD + ty + 16 * r];
            vr[r] = Vs[j * DD + tx + 16 * r];
        }
#pragma unroll
        for (int r = 0; r < 4; r++)
#pragma unroll
            for (int s = 0; s < 4; s++) acc[r][s] += kr[r] * vr[s];
    }

    float* P = g_P + ((size_t)p * NC + c) * DD * MM;
#pragma unroll
    for (int r = 0; r < 4; r++)
#pragma unroll
        for (int s = 0; s < 4; s++)
            P[(ty + 16 * r) * MM + tx + 16 * s] = acc[r][s];

    if (tid < DD) {
        float s = 0.f;
        for (int j = 0; j < CC; j++) s += Ks[j * DD + tid];
        g_ks[(p * NC + c) * DD + tid] = s;
    }
}

// ---------------------------------------------------------------------------
// Kernel 2: exclusive prefix over chunks, in place. blocks = NP, 256 threads.
// ---------------------------------------------------------------------------
__global__ void k2_prefix() {
    int p = blockIdx.x, tid = threadIdx.x;
    float run[16];
#pragma unroll
    for (int r = 0; r < 16; r++) run[r] = 0.f;

    for (int c = 0; c < NC; c++) {
        float* P = g_P + ((size_t)p * NC + c) * DD * MM;
#pragma unroll
        for (int r = 0; r < 16; r++) {
            int e = tid + 256 * r;
            float t = P[e];
            P[e] = run[r];
            run[r] += t;
        }
    }
    if (tid < DD) {
        float rs = 0.f;
        for (int c = 0; c < NC; c++) {
            float* Kp = g_ks + (p * NC + c) * DD;
            float t = Kp[tid];
            Kp[tid] = rs;
            rs += t;
        }
    }
}

// ---------------------------------------------------------------------------
// Kernel 3: per-chunk output. blocks = NP*NC, 256 threads.
// smem (padded strides for conflict-free LDS): ~152 KB dynamic.
// ---------------------------------------------------------------------------
#define QS_STRIDE 68
#define AT_STRIDE 132
#define SS_STRIDE 68
#define K3_SMEM ((CC*QS_STRIDE + CC*QS_STRIDE + CC*AT_STRIDE + DD*SS_STRIDE + DD + CC) * 4)

__global__ void k3_out(const float* __restrict__ qin,
                       const float* __restrict__ kin,
                       const float* __restrict__ vin,
                       float* __restrict__ out) {
    extern __shared__ float sm[];
    float* Qs = sm;                       // [CC][QS_STRIDE] phi(Q)
    float* KV = Qs + CC * QS_STRIDE;      // [CC][QS_STRIDE] phi(K), later V
    float* At = KV + CC * QS_STRIDE;      // [CC][AT_STRIDE] masked attn
    float* Ss = At + CC * AT_STRIDE;      // [DD][SS_STRIDE] S_prev
    float* kc = Ss + DD * SS_STRIDE;      // [DD] kcum_prev
    float* zz = kc + DD;                  // [CC] normalizer

    int blk = blockIdx.x;
    int p = blk >> 4, c = blk & (NC - 1);
    int n = p >> 4, h = p & 15;
    int tid = threadIdx.x;

    size_t base = ((size_t)(n * LL + c * CC) * HH + h) * DD;

    // load phi(Q), phi(K)
    for (int e = tid; e < CC * DD / 4; e += 256) {
        int j = e >> 4, dd = e & 15;
        size_t g = base + (size_t)j * HH * DD + dd * 4;
        float4 qv = *(const float4*)(qin + g);
        qv.x = phi(qv.x); qv.y = phi(qv.y); qv.z = phi(qv.z); qv.w = phi(qv.w);
        *(float4*)(Qs + j * QS_STRIDE + dd * 4) = qv;
        float4 kv = *(const float4*)(kin + g);
        kv.x = phi(kv.x); kv.y = phi(kv.y); kv.z = phi(kv.z); kv.w = phi(kv.w);
        *(float4*)(KV + j * QS_STRIDE + dd * 4) = kv;
    }
    // load S_prev, kcum_prev
    {
        const float* P = g_P + ((size_t)p * NC + c) * DD * MM;
        for (int e = tid; e < DD * MM / 4; e += 256) {
            int d = e >> 4, mm4 = e & 15;
            *(float4*)(Ss + d * SS_STRIDE + mm4 * 4) = *(const float4*)(P + d * MM + mm4 * 4);
        }
        if (tid < DD) kc[tid] = g_ks[(p * NC + c) * DD + tid];
    }
    __syncthreads();

    // attn = phi(Q) phi(K)^T, masked. Interleaved 8x8 tile per thread.
    {
        int ty = tid >> 4, tx = tid & 15;
        float a[8][8] = {};
        for (int dd = 0; dd < DD / 4; dd++) {
            float4 qv[8], kv[8];
#pragma unroll
            for (int r = 0; r < 8; r++) qv[r] = *(float4*)(Qs + (ty + 16 * r) * QS_STRIDE + dd * 4);
#pragma unroll
            for (int s = 0; s < 8; s++) kv[s] = *(float4*)(KV + (tx + 16 * s) * QS_STRIDE + dd * 4);
#pragma unroll
            for (int r = 0; r < 8; r++)
#pragma unroll
                for (int s = 0; s < 8; s++)
                    a[r][s] += qv[r].x * kv[s].x + qv[r].y * kv[s].y +
                               qv[r].z * kv[s].z + qv[r].w * kv[s].w;
        }
#pragma unroll
        for (int r = 0; r < 8; r++) {
            int i = ty + 16 * r;
#pragma unroll
            for (int s = 0; s < 8; s++) {
                int j = tx + 16 * s;
                At[i * AT_STRIDE + j] = (j <= i) ? a[r][s] : 0.f;
            }
        }
    }
    __syncthreads();

    // z[i] = rowsum(At[i]) + phi(q_i).kcum_prev + eps   (threads 0..127)
    if (tid < CC) {
        float s = EPSV;
        for (int j = 0; j < CC; j++) s += At[tid * AT_STRIDE + j];
        float qk = 0.f;
        for (int d = 0; d < DD; d++) qk += Qs[tid * QS_STRIDE + d] * kc[d];
        zz[tid] = s + qk;
    }
    // overlap: reload KV region with V (K no longer needed)
    for (int e = tid; e < CC * DD / 4; e += 256) {
        int j = e >> 4, dd = e & 15;
        size_t g = base + (size_t)j * HH * DD + dd * 4;
        *(float4*)(KV + j * QS_STRIDE + dd * 4) = *(const float4*)(vin + g);
    }
    __syncthreads();

    // out[i][m] = (sum_j At[i][j] V[j][m] + sum_d Qs[i][d] Ss[d][m]) / z[i]
    {
        int ty2 = tid >> 3, tx2 = tid & 7;   // 32 row-groups x 8 col-groups
        int m0 = tx2 * 8;
        float acc[4][8] = {};
        for (int j = 0; j < CC; j++) {
            float4 v0 = *(float4*)(KV + j * QS_STRIDE + m0);
            float4 v1 = *(float4*)(KV + j * QS_STRIDE + m0 + 4);
#pragma unroll
            for (int r = 0; r < 4; r++) {
                float av = At[(ty2 + 32 * r) * AT_STRIDE + j];
                acc[r][0] += av * v0.x; acc[r][1] += av * v0.y;
                acc[r][2] += av * v0.z; acc[r][3] += av * v0.w;
                acc[r][4] += av * v1.x; acc[r][5] += av * v1.y;
                acc[r][6] += av * v1.z; acc[r][7] += av * v1.w;
            }
        }
        for (int d = 0; d < DD; d++) {
            float4 s0 = *(float4*)(Ss + d * SS_STRIDE + m0);
            float4 s1 = *(float4*)(Ss + d * SS_STRIDE + m0 + 4);
#pragma unroll
            for (int r = 0; r < 4; r++) {
                float qv = Qs[(ty2 + 32 * r) * QS_STRIDE + d];
                acc[r][0] += qv * s0.x; acc[r][1] += qv * s0.y;
                acc[r][2] += qv * s0.z; acc[r][3] += qv * s0.w;
                acc[r][4] += qv * s1.x; acc[r][5] += qv * s1.y;
                acc[r][6] += qv * s1.z; acc[r][7] += qv * s1.w;
            }
        }
#pragma unroll
        for (int r = 0; r < 4; r++) {
            int i = ty2 + 32 * r;
            float invz = 1.f / zz[i];
            float4 o0, o1;
            o0.x = acc[r][0] * invz; o0.y = acc[r][1] * invz;
            o0.z = acc[r][2] * invz; o0.w = acc[r][3] * invz;
            o1.x = acc[r][4] * invz; o1.y = acc[r][5] * invz;
            o1.z = acc[r][6] * invz; o1.w = acc[r][7] * invz;
            size_t g = base + (size_t)i * HH * DD + m0;
            *(float4*)(out + g) = o0;
            *(float4*)(out + g + 4) = o1;
        }
    }
}

// ---------------------------------------------------------------------------

extern "C" void kernel_launch(void* const* d_in, const int* in_sizes, int n_in,
                              void* d_out, int out_size) {
    const float* q = (const float*)d_in[0];
    const float* k = (const float*)d_in[1];
    const float* v = (const float*)d_in[2];
    float* out = (float*)d_out;

    cudaFuncSetAttribute(k1_chunk_kv, cudaFuncAttributeMaxDynamicSharedMemorySize,
                         2 * CC * DD * 4);
    cudaFuncSetAttribute(k3_out, cudaFuncAttributeMaxDynamicSharedMemorySize,
                         K3_SMEM);

    k1_chunk_kv<<<NP * NC, 256, 2 * CC * DD * 4>>>(k, v);
    k2_prefix<<<NP, 256>>>();
    k3_out<<<NP * NC, 256, K3_SMEM>>>(q, k, v, out);
}

// round 2
// speedup vs baseline: 1.7392x; 1.7392x over previous
#include <cuda_runtime.h>
#include <cstdint>

// Causal linear attention (elu+1), chunked-parallel, tf32 tensor-core path.
// [B=8, L=2048, H=16, D=64], M=64, chunk C=128.

#define BB 8
#define LL 2048
#define HH 16
#define DD 64
#define MM 64
#define CC 128
#define NC (LL/CC)      // 16
#define NP (BB*HH)      // 128
#define EPSV 1e-6f

__device__ float g_P[(size_t)NP * NC * DD * MM];   // 33.5 MB scratch
__device__ float g_ks[NP * NC * DD];

__device__ __forceinline__ float phi(float x) {
    return x > 0.f ? x + 1.f : __expf(x);
}
__device__ __forceinline__ float tf32r(float x) {
    uint32_t u; asm("cvt.rna.tf32.f32 %0, %1;" : "=r"(u) : "f"(x));
    return __uint_as_float(u);
}
#define AS_U(x) __float_as_uint(x)

__device__ __forceinline__ void mma8(float* c, uint32_t a0, uint32_t a1,
                                     uint32_t a2, uint32_t a3,
                                     uint32_t b0, uint32_t b1) {
    asm volatile(
        "mma.sync.aligned.m16n8k8.row.col.f32.tf32.tf32.f32 "
        "{%0,%1,%2,%3}, {%4,%5,%6,%7}, {%8,%9}, {%0,%1,%2,%3};"
        : "+f"(c[0]), "+f"(c[1]), "+f"(c[2]), "+f"(c[3])
        : "r"(a0), "r"(a1), "r"(a2), "r"(a3), "r"(b0), "r"(b1));
}

// ---------------------------------------------------------------------------
// Kernel 1: P_c = phi(K_c)^T V_c  (64x64), ksum_c.  2048 blocks x 256 thr.
// Ks,Vs stride 72 (==8 mod 32): frag loads bank = 8t+g  -> conflict-free.
// ---------------------------------------------------------------------------
#define K1_SMEM ((128*72 + 128*72 + 64*68) * 4)

__global__ void __launch_bounds__(256, 2)
k1_chunk_kv(const float* __restrict__ kin, const float* __restrict__ vin) {
    extern __shared__ float sm[];
    float* Ks = sm;               // [128][72]
    float* Vs = Ks + 128 * 72;    // [128][72]
    float* Ps = Vs + 128 * 72;    // [64][68] staging

    int blk = blockIdx.x;
    int p = blk >> 4, c = blk & 15;
    int n = p >> 4, h = p & 15;
    int tid = threadIdx.x;
    size_t base = ((size_t)(n * LL + c * CC) * HH + h) * DD;

    for (int e = tid; e < CC * DD / 4; e += 256) {
        int j = e >> 4, d4 = (e & 15) * 4;
        size_t g = base + (size_t)j * HH * DD + d4;
        float4 kv = *(const float4*)(kin + g);
        kv.x = tf32r(phi(kv.x)); kv.y = tf32r(phi(kv.y));
        kv.z = tf32r(phi(kv.z)); kv.w = tf32r(phi(kv.w));
        *(float4*)(Ks + j * 72 + d4) = kv;
        float4 vv = *(const float4*)(vin + g);
        vv.x = tf32r(vv.x); vv.y = tf32r(vv.y);
        vv.z = tf32r(vv.z); vv.w = tf32r(vv.w);
        *(float4*)(Vs + j * 72 + d4) = vv;
    }
    __syncthreads();

    int w = tid >> 5, lane = tid & 31, gq = lane >> 2, t = lane & 3;
    int d0 = (w >> 1) * 16;          // A(=K^T) row tile
    int nb = (w & 1) * 32;           // N half

    float acc[4][4];
#pragma unroll
    for (int i = 0; i < 4; i++)
#pragma unroll
        for (int j = 0; j < 4; j++) acc[i][j] = 0.f;

#pragma unroll
    for (int kt = 0; kt < 16; kt++) {
        int k0 = kt * 8;
        // A[d][j] = Ks[j][d]
        uint32_t a0 = AS_U(Ks[(k0 + t) * 72 + d0 + gq]);
        uint32_t a1 = AS_U(Ks[(k0 + t) * 72 + d0 + gq + 8]);
        uint32_t a2 = AS_U(Ks[(k0 + t + 4) * 72 + d0 + gq]);
        uint32_t a3 = AS_U(Ks[(k0 + t + 4) * 72 + d0 + gq + 8]);
#pragma unroll
        for (int nt = 0; nt < 4; nt++) {
            int n0 = nb + nt * 8;
            uint32_t b0 = AS_U(Vs[(k0 + t) * 72 + n0 + gq]);
            uint32_t b1 = AS_U(Vs[(k0 + t + 4) * 72 + n0 + gq]);
            mma8(acc[nt], a0, a1, a2, a3, b0, b1);
        }
    }
    // stage P tile
#pragma unroll
    for (int nt = 0; nt < 4; nt++) {
        int n0 = nb + nt * 8 + 2 * t;
        *(float2*)(Ps + (d0 + gq) * 68 + n0)     = make_float2(acc[nt][0], acc[nt][1]);
        *(float2*)(Ps + (d0 + gq + 8) * 68 + n0) = make_float2(acc[nt][2], acc[nt][3]);
    }
    if (tid < DD) {
        float s = 0.f;
        for (int j = 0; j < CC; j++) s += Ks[j * 72 + tid];
        g_ks[(p * NC + c) * DD + tid] = s;
    }
    __syncthreads();

    float* P = g_P + ((size_t)p * NC + c) * DD * MM;
    for (int e = tid; e < DD * MM / 4; e += 256) {
        int r = e >> 4, c4 = (e & 15) * 4;
        *(float4*)(P + r * MM + c4) = *(float4*)(Ps + r * 68 + c4);
    }
}

// ---------------------------------------------------------------------------
// Kernel 2: exclusive prefix over the 16 chunks. 2048 blocks x 256 thr.
// ---------------------------------------------------------------------------
__global__ void k2_prefix() {
    int b = blockIdx.x;
    int p = b >> 4, seg = b & 15;
    int e = seg * 256 + threadIdx.x;
    float* base = g_P + (size_t)p * NC * DD * MM + e;
    float run = 0.f;
#pragma unroll
    for (int c = 0; c < NC; c++) {
        float tv = base[c * DD * MM];
        base[c * DD * MM] = run;
        run += tv;
    }
    if (seg == 0 && threadIdx.x < DD) {
        float rs = 0.f;
        for (int c = 0; c < NC; c++) {
            float* kp = g_ks + (p * NC + c) * DD + threadIdx.x;
            float tv = *kp; *kp = rs; rs += tv;
        }
    }
}

// ---------------------------------------------------------------------------
// Kernel 3: A = tril(phi(Q)phi(K)^T); out = (A V + phi(Q) S)/z.
// 2048 blocks x 256 thr.  A-operand strides ==4 mod 32, B-operand ==8 mod 32.
// ---------------------------------------------------------------------------
#define K3_SMEM ((128*68 + 128*72 + 128*132 + 64*72 + 64 + 128) * 4)

__global__ void __launch_bounds__(256, 1)
k3_out(const float* __restrict__ qin, const float* __restrict__ kin,
       const float* __restrict__ vin, float* __restrict__ out) {
    extern __shared__ float sm[];
    float* Qs = sm;                  // [128][68] phi(Q) tf32
    float* KV = Qs + 128 * 68;       // phi(K) stride 68, then V stride 72
    float* At = KV + 128 * 72;       // [128][132] masked attn (tf32)
    float* Ss = At + 128 * 132;      // [64][72] S_prev tf32
    float* kc = Ss + 64 * 72;        // [64]
    float* zz = kc + 64;             // [128]

    int blk = blockIdx.x;
    int p = blk >> 4, c = blk & 15;
    int n = p >> 4, h = p & 15;
    int tid = threadIdx.x;
    size_t base = ((size_t)(n * LL + c * CC) * HH + h) * DD;

    for (int e = tid; e < CC * DD / 4; e += 256) {
        int j = e >> 4, d4 = (e & 15) * 4;
        size_t g = base + (size_t)j * HH * DD + d4;
        float4 qv = *(const float4*)(qin + g);
        qv.x = tf32r(phi(qv.x)); qv.y = tf32r(phi(qv.y));
        qv.z = tf32r(phi(qv.z)); qv.w = tf32r(phi(qv.w));
        *(float4*)(Qs + j * 68 + d4) = qv;
        float4 kv = *(const float4*)(kin + g);
        kv.x = tf32r(phi(kv.x)); kv.y = tf32r(phi(kv.y));
        kv.z = tf32r(phi(kv.z)); kv.w = tf32r(phi(kv.w));
        *(float4*)(KV + j * 68 + d4) = kv;
    }
    {
        const float* P = g_P + ((size_t)p * NC + c) * DD * MM;
        for (int e = tid; e < DD * MM / 4; e += 256) {
            int r = e >> 4, c4 = (e & 15) * 4;
            float4 sv = *(const float4*)(P + r * MM + c4);
            sv.x = tf32r(sv.x); sv.y = tf32r(sv.y);
            sv.z = tf32r(sv.z); sv.w = tf32r(sv.w);
            *(float4*)(Ss + r * 72 + c4) = sv;
        }
        if (tid < DD) kc[tid] = g_ks[(p * NC + c) * DD + tid];
    }
    __syncthreads();

    int w = tid >> 5, lane = tid & 31, gq = lane >> 2, t = lane & 3;
    int m0 = w * 16;
    int ilo = m0 + gq, ihi = ilo + 8;
    const int NT1 = 2 * w + 2;      // triangular: only tiles j0 <= m0+15

    // ---- GEMM1: A = phi(Q) phi(K)^T  (M=128,N=128,K=64) ----
    float acc[16][4];
#pragma unroll
    for (int i = 0; i < 16; i++)
#pragma unroll
        for (int j = 0; j < 4; j++) acc[i][j] = 0.f;

#pragma unroll
    for (int kt = 0; kt < 8; kt++) {
        int k0 = kt * 8;
        uint32_t a0 = AS_U(Qs[ilo * 68 + k0 + t]);
        uint32_t a1 = AS_U(Qs[ihi * 68 + k0 + t]);
        uint32_t a2 = AS_U(Qs[ilo * 68 + k0 + t + 4]);
        uint32_t a3 = AS_U(Qs[ihi * 68 + k0 + t + 4]);
#pragma unroll
        for (int nt = 0; nt < 16; nt++) {
            if (nt >= NT1) break;
            int n0 = nt * 8;
            uint32_t b0 = AS_U(KV[(n0 + gq) * 68 + k0 + t]);
            uint32_t b1 = AS_U(KV[(n0 + gq) * 68 + k0 + t + 4]);
            mma8(acc[nt], a0, a1, a2, a3, b0, b1);
        }
    }

    // mask + row sums + store tf32(A) to At
    float rlo = 0.f, rhi = 0.f;
#pragma unroll
    for (int nt = 0; nt < 16; nt++) {
        if (nt >= NT1) break;
        int jc0 = nt * 8 + 2 * t, jc1 = jc0 + 1;
        float c0 = (jc0 <= ilo) ? acc[nt][0] : 0.f;
        float c1 = (jc1 <= ilo) ? acc[nt][1] : 0.f;
        float c2 = (jc0 <= ihi) ? acc[nt][2] : 0.f;
        float c3 = (jc1 <= ihi) ? acc[nt][3] : 0.f;
        rlo += c0 + c1; rhi += c2 + c3;
        *(float2*)(At + ilo * 132 + jc0) = make_float2(tf32r(c0), tf32r(c1));
        *(float2*)(At + ihi * 132 + jc0) = make_float2(tf32r(c2), tf32r(c3));
    }
    rlo += __shfl_xor_sync(0xffffffffu, rlo, 1);
    rlo += __shfl_xor_sync(0xffffffffu, rlo, 2);
    rhi += __shfl_xor_sync(0xffffffffu, rhi, 1);
    rhi += __shfl_xor_sync(0xffffffffu, rhi, 2);
    if (t == 0) { zz[ilo] = rlo; zz[ihi] = rhi; }
    __syncthreads();

    // reload KV region with V (stride 72); finalize z
    for (int e = tid; e < CC * DD / 4; e += 256) {
        int j = e >> 4, d4 = (e & 15) * 4;
        size_t g = base + (size_t)j * HH * DD + d4;
        float4 vv = *(const float4*)(vin + g);
        vv.x = tf32r(vv.x); vv.y = tf32r(vv.y);
        vv.z = tf32r(vv.z); vv.w = tf32r(vv.w);
        *(float4*)(KV + j * 72 + d4) = vv;
    }
    if (tid < CC) {
        float s = zz[tid] + EPSV;
#pragma unroll
        for (int d = 0; d < DD; d++) s += Qs[tid * 68 + d] * kc[d];
        zz[tid] = s;
    }
    __syncthreads();

    // ---- GEMM2: out = At*V + Qs*Ss  (M=128,N=64, K=128(+tri-skip)+64) ----
    float acc2[8][4];
#pragma unroll
    for (int i = 0; i < 8; i++)
#pragma unroll
        for (int j = 0; j < 4; j++) acc2[i][j] = 0.f;

#pragma unroll
    for (int kt = 0; kt < 16; kt++) {
        if (kt >= NT1) break;       // At cols beyond m0+15 are zero
        int k0 = kt * 8;
        uint32_t a0 = AS_U(At[ilo * 132 + k0 + t]);
        uint32_t a1 = AS_U(At[ihi * 132 + k0 + t]);
        uint32_t a2 = AS_U(At[ilo * 132 + k0 + t + 4]);
        uint32_t a3 = AS_U(At[ihi * 132 + k0 + t + 4]);
#pragma unroll
        for (int nt = 0; nt < 8; nt++) {
            int n0 = nt * 8;
            uint32_t b0 = AS_U(KV[(k0 + t) * 72 + n0 + gq]);
            uint32_t b1 = AS_U(KV[(k0 + t + 4) * 72 + n0 + gq]);
            mma8(acc2[nt], a0, a1, a2, a3, b0, b1);
        }
    }
#pragma unroll
    for (int kt = 0; kt < 8; kt++) {
        int k0 = kt * 8;
        uint32_t a0 = AS_U(Qs[ilo * 68 + k0 + t]);
        uint32_t a1 = AS_U(Qs[ihi * 68 + k0 + t]);
        uint32_t a2 = AS_U(Qs[ilo * 68 + k0 + t + 4]);
        uint32_t a3 = AS_U(Qs[ihi * 68 + k0 + t + 4]);
#pragma unroll
        for (int nt = 0; nt < 8; nt++) {
            int n0 = nt * 8;
            uint32_t b0 = AS_U(Ss[(k0 + t) * 72 + n0 + gq]);
            uint32_t b1 = AS_U(Ss[(k0 + t + 4) * 72 + n0 + gq]);
            mma8(acc2[nt], a0, a1, a2, a3, b0, b1);
        }
    }

    // epilogue: divide by z, stage in At (own rows), coalesced STG.128
    float izlo = 1.f / zz[ilo], izhi = 1.f / zz[ihi];
#pragma unroll
    for (int nt = 0; nt < 8; nt++) {
        int n0 = nt * 8 + 2 * t;
        *(float2*)(At + ilo * 132 + n0) = make_float2(acc2[nt][0] * izlo, acc2[nt][1] * izlo);
        *(float2*)(At + ihi * 132 + n0) = make_float2(acc2[nt][2] * izhi, acc2[nt][3] * izhi);
    }
    __syncwarp();
#pragma unroll
    for (int it = 0; it < 8; it++) {
        int idx = it * 32 + lane;       // 256 float4 = 16 rows x 16
        int r = idx >> 4, c4 = (idx & 15) * 4;
        float4 vvv = *(float4*)(At + (m0 + r) * 132 + c4);
        *(float4*)(out + base + (size_t)(m0 + r) * HH * DD + c4) = vvv;
    }
}

// ---------------------------------------------------------------------------

extern "C" void kernel_launch(void* const* d_in, const int* in_sizes, int n_in,
                              void* d_out, int out_size) {
    const float* q = (const float*)d_in[0];
    const float* k = (const float*)d_in[1];
    const float* v = (const float*)d_in[2];
    float* out = (float*)d_out;

    cudaFuncSetAttribute(k1_chunk_kv, cudaFuncAttributeMaxDynamicSharedMemorySize, K1_SMEM);
    cudaFuncSetAttribute(k3_out, cudaFuncAttributeMaxDynamicSharedMemorySize, K3_SMEM);

    k1_chunk_kv<<<NP * NC, 256, K1_SMEM>>>(k, v);
    k2_prefix<<<NP * 16, 256>>>();
    k3_out<<<NP * NC, 256, K3_SMEM>>>(q, k, v, out);
}

// round 3
// speedup vs baseline: 2.1220x; 1.2201x over previous
#include <cuda_runtime.h>
#include <cstdint>

// Fused causal linear attention (elu+1), chunked, tf32 mma, persistent state.
// [B=8, L=2048, H=16, D=64], M=64, chunk C=128. One block per (batch,head).

#define BB 8
#define LL 2048
#define HH 16
#define DD 64
#define MM 64
#define CC 128
#define NC (LL/CC)      // 16
#define NP (BB*HH)      // 128
#define EPSV 1e-6f

__device__ __forceinline__ float phi(float x) {
    return x > 0.f ? x + 1.f : __expf(x);
}
__device__ __forceinline__ float tf32r(float x) {
    uint32_t u; asm("cvt.rna.tf32.f32 %0, %1;" : "=r"(u) : "f"(x));
    return __uint_as_float(u);
}
#define AS_U(x) __float_as_uint(x)

__device__ __forceinline__ void mma8(float* c, uint32_t a0, uint32_t a1,
                                     uint32_t a2, uint32_t a3,
                                     uint32_t b0, uint32_t b1) {
    asm volatile(
        "mma.sync.aligned.m16n8k8.row.col.f32.tf32.tf32.f32 "
        "{%0,%1,%2,%3}, {%4,%5,%6,%7}, {%8,%9}, {%0,%1,%2,%3};"
        : "+f"(c[0]), "+f"(c[1]), "+f"(c[2]), "+f"(c[3])
        : "r"(a0), "r"(a1), "r"(a2), "r"(a3), "r"(b0), "r"(b1));
}

// smem floats:
//  Qs[128][68] phi(Q) tf32          (A-operand: stride==4 mod 32)
//  Ks[128][68] phi(K) tf32          (B GEMM1 / transposed-A KtV)
//  Vs[128][72] V tf32               (B-operand: stride==8 mod 32)
//  At[128][132] masked attn / out staging
//  Ss[64][72]  running state S (fp32)
//  kc[64]      running ksum (fp32)
#define SMEM_FLOATS (128*68 + 128*68 + 128*72 + 128*132 + 64*72 + 64)
#define SMEM_BYTES  (SMEM_FLOATS * 4)

__global__ void __launch_bounds__(256, 1)
fused_lin_attn(const float* __restrict__ qin, const float* __restrict__ kin,
               const float* __restrict__ vin, float* __restrict__ out) {
    extern __shared__ float sm[];
    float* Qs = sm;
    float* Ks = Qs + 128 * 68;
    float* Vs = Ks + 128 * 68;
    float* At = Vs + 128 * 72;
    float* Ss = At + 128 * 132;
    float* kc = Ss + 64 * 72;

    int p = blockIdx.x;
    int n = p >> 4, h = p & 15;
    int tid = threadIdx.x;
    int w = tid >> 5, lane = tid & 31, gq = lane >> 2, t = lane & 3;
    int m0 = w * 16;
    int ilo = m0 + gq, ihi = ilo + 8;
    const int NT1 = 2 * w + 2;          // triangular tile count for this warp
    int d0 = (w >> 1) * 16;             // KtV mapping
    int nb = (w & 1) * 32;

    // zero running state
    for (int e = tid; e < 64 * 72; e += 256) Ss[e] = 0.f;
    if (tid < DD) kc[tid] = 0.f;
    __syncthreads();

    size_t pbase = ((size_t)n * LL * HH + h) * DD;

    for (int c = 0; c < NC; c++) {
        size_t base = pbase + (size_t)(c * CC) * HH * DD;

        // ---- load chunk: phi+tf32 Q,K ; tf32 V ----
        for (int e = tid; e < CC * DD / 4; e += 256) {
            int j = e >> 4, d4 = (e & 15) * 4;
            size_t g = base + (size_t)j * HH * DD + d4;
            float4 qv = *(const float4*)(qin + g);
            qv.x = tf32r(phi(qv.x)); qv.y = tf32r(phi(qv.y));
            qv.z = tf32r(phi(qv.z)); qv.w = tf32r(phi(qv.w));
            *(float4*)(Qs + j * 68 + d4) = qv;
            float4 kv = *(const float4*)(kin + g);
            kv.x = tf32r(phi(kv.x)); kv.y = tf32r(phi(kv.y));
            kv.z = tf32r(phi(kv.z)); kv.w = tf32r(phi(kv.w));
            *(float4*)(Ks + j * 68 + d4) = kv;
            float4 vv = *(const float4*)(vin + g);
            vv.x = tf32r(vv.x); vv.y = tf32r(vv.y);
            vv.z = tf32r(vv.z); vv.w = tf32r(vv.w);
            *(float4*)(Vs + j * 72 + d4) = vv;
        }
        __syncthreads();                                   // S1

        // ---- GEMM1: A = phi(Q) phi(K)^T  (warp-private rows m0..m0+15) ----
        float acc[16][4];
#pragma unroll
        for (int i = 0; i < 16; i++)
#pragma unroll
            for (int j = 0; j < 4; j++) acc[i][j] = 0.f;

#pragma unroll
        for (int kt = 0; kt < 8; kt++) {
            int k0 = kt * 8;
            uint32_t a0 = AS_U(Qs[ilo * 68 + k0 + t]);
            uint32_t a1 = AS_U(Qs[ihi * 68 + k0 + t]);
            uint32_t a2 = AS_U(Qs[ilo * 68 + k0 + t + 4]);
            uint32_t a3 = AS_U(Qs[ihi * 68 + k0 + t + 4]);
#pragma unroll
            for (int nt = 0; nt < 16; nt++) {
                if (nt >= NT1) break;
                int n0 = nt * 8;
                uint32_t b0 = AS_U(Ks[(n0 + gq) * 68 + k0 + t]);
                uint32_t b1 = AS_U(Ks[(n0 + gq) * 68 + k0 + t + 4]);
                mma8(acc[nt], a0, a1, a2, a3, b0, b1);
            }
        }

        // ---- mask + row sums + store tf32(A) to At (own rows) ----
        float rlo = 0.f, rhi = 0.f;
#pragma unroll
        for (int nt = 0; nt < 16; nt++) {
            if (nt >= NT1) break;
            int jc0 = nt * 8 + 2 * t, jc1 = jc0 + 1;
            float c0 = (jc0 <= ilo) ? acc[nt][0] : 0.f;
            float c1 = (jc1 <= ilo) ? acc[nt][1] : 0.f;
            float c2 = (jc0 <= ihi) ? acc[nt][2] : 0.f;
            float c3 = (jc1 <= ihi) ? acc[nt][3] : 0.f;
            rlo += c0 + c1; rhi += c2 + c3;
            *(float2*)(At + ilo * 132 + jc0) = make_float2(tf32r(c0), tf32r(c1));
            *(float2*)(At + ihi * 132 + jc0) = make_float2(tf32r(c2), tf32r(c3));
        }
        // z = rowsum + q.kcum + eps, fully warp-local (reduce over quad)
        float qlo = 0.f, qhi = 0.f;
#pragma unroll
        for (int i = 0; i < 16; i++) {
            int d = t * 16 + i;
            float kcd = kc[d];
            qlo += Qs[ilo * 68 + d] * kcd;
            qhi += Qs[ihi * 68 + d] * kcd;
        }
        rlo += qlo; rhi += qhi;
        rlo += __shfl_xor_sync(0xffffffffu, rlo, 1);
        rlo += __shfl_xor_sync(0xffffffffu, rlo, 2);
        rhi += __shfl_xor_sync(0xffffffffu, rhi, 1);
        rhi += __shfl_xor_sync(0xffffffffu, rhi, 2);
        float izlo = 1.f / (rlo + EPSV);
        float izhi = 1.f / (rhi + EPSV);

        // ---- GEMM2: out = At*V + Qs*S_prev ----
        float acc2[8][4];
#pragma unroll
        for (int i = 0; i < 8; i++)
#pragma unroll
            for (int j = 0; j < 4; j++) acc2[i][j] = 0.f;

#pragma unroll
        for (int kt = 0; kt < 16; kt++) {
            if (kt >= NT1) break;       // At cols beyond m0+15 are zero
            int k0 = kt * 8;
            uint32_t a0 = AS_U(At[ilo * 132 + k0 + t]);
            uint32_t a1 = AS_U(At[ihi * 132 + k0 + t]);
            uint32_t a2 = AS_U(At[ilo * 132 + k0 + t + 4]);
            uint32_t a3 = AS_U(At[ihi * 132 + k0 + t + 4]);
#pragma unroll
            for (int nt = 0; nt < 8; nt++) {
                int n0 = nt * 8;
                uint32_t b0 = AS_U(Vs[(k0 + t) * 72 + n0 + gq]);
                uint32_t b1 = AS_U(Vs[(k0 + t + 4) * 72 + n0 + gq]);
                mma8(acc2[nt], a0, a1, a2, a3, b0, b1);
            }
        }
        if (c > 0) {
#pragma unroll
            for (int kt = 0; kt < 8; kt++) {
                int k0 = kt * 8;
                uint32_t a0 = AS_U(Qs[ilo * 68 + k0 + t]);
                uint32_t a1 = AS_U(Qs[ihi * 68 + k0 + t]);
                uint32_t a2 = AS_U(Qs[ilo * 68 + k0 + t + 4]);
                uint32_t a3 = AS_U(Qs[ihi * 68 + k0 + t + 4]);
#pragma unroll
                for (int nt = 0; nt < 8; nt++) {
                    int n0 = nt * 8;
                    uint32_t b0 = AS_U(tf32r(Ss[(k0 + t) * 72 + n0 + gq]));
                    uint32_t b1 = AS_U(tf32r(Ss[(k0 + t + 4) * 72 + n0 + gq]));
                    mma8(acc2[nt], a0, a1, a2, a3, b0, b1);
                }
            }
        }

        // ---- KtV for state update (into regs) ----
        float acc3[4][4];
#pragma unroll
        for (int i = 0; i < 4; i++)
#pragma unroll
            for (int j = 0; j < 4; j++) acc3[i][j] = 0.f;
#pragma unroll
        for (int kt = 0; kt < 16; kt++) {
            int k0 = kt * 8;
            uint32_t a0 = AS_U(Ks[(k0 + t) * 68 + d0 + gq]);
            uint32_t a1 = AS_U(Ks[(k0 + t) * 68 + d0 + gq + 8]);
            uint32_t a2 = AS_U(Ks[(k0 + t + 4) * 68 + d0 + gq]);
            uint32_t a3 = AS_U(Ks[(k0 + t + 4) * 68 + d0 + gq + 8]);
#pragma unroll
            for (int nt = 0; nt < 4; nt++) {
                int n0 = nb + nt * 8;
                uint32_t b0 = AS_U(Vs[(k0 + t) * 72 + n0 + gq]);
                uint32_t b1 = AS_U(Vs[(k0 + t + 4) * 72 + n0 + gq]);
                mma8(acc3[nt], a0, a1, a2, a3, b0, b1);
            }
        }
        // ksum partial (warps 0..1 — lightest GEMM1 load)
        float ksum = 0.f;
        if (tid < DD) {
#pragma unroll
            for (int j = 0; j < CC; j++) ksum += Ks[j * 68 + tid];
        }
        __syncthreads();                                   // S2

        // ---- state update ----
#pragma unroll
        for (int nt = 0; nt < 4; nt++) {
            int n0 = nb + nt * 8 + 2 * t;
            float2* s0 = (float2*)(Ss + (d0 + gq) * 72 + n0);
            float2* s1 = (float2*)(Ss + (d0 + gq + 8) * 72 + n0);
            float2 v0 = *s0, v1 = *s1;
            v0.x += acc3[nt][0]; v0.y += acc3[nt][1];
            v1.x += acc3[nt][2]; v1.y += acc3[nt][3];
            *s0 = v0; *s1 = v1;
        }
        if (tid < DD) kc[tid] += ksum;

        // ---- epilogue: divide, stage in At (own rows), coalesced STG ----
#pragma unroll
        for (int nt = 0; nt < 8; nt++) {
            int n0 = nt * 8 + 2 * t;
            *(float2*)(At + ilo * 132 + n0) =
                make_float2(acc2[nt][0] * izlo, acc2[nt][1] * izlo);
            *(float2*)(At + ihi * 132 + n0) =
                make_float2(acc2[nt][2] * izhi, acc2[nt][3] * izhi);
        }
        __syncwarp();
#pragma unroll
        for (int it = 0; it < 8; it++) {
            int idx = it * 32 + lane;           // 16 rows x 16 float4
            int r = idx >> 4, c4 = (idx & 15) * 4;
            float4 vvv = *(float4*)(At + (m0 + r) * 132 + c4);
            *(float4*)(out + base + (size_t)(m0 + r) * HH * DD + c4) = vvv;
        }
        // no end barrier needed: next-iter smem writes (Qs/Ks/Vs) are guarded
        // by S1; At/Ss/kc hazards are warp-local or guarded by S1/S2.
    }
}

// ---------------------------------------------------------------------------

extern "C" void kernel_launch(void* const* d_in, const int* in_sizes, int n_in,
                              void* d_out, int out_size) {
    const float* q = (const float*)d_in[0];
    const float* k = (const float*)d_in[1];
    const float* v = (const float*)d_in[2];
    float* out = (float*)d_out;

    cudaFuncSetAttribute(fused_lin_attn,
                         cudaFuncAttributeMaxDynamicSharedMemorySize, SMEM_BYTES);
    fused_lin_attn<<<NP, 256, SMEM_BYTES>>>(q, k, v, out);
}

// round 4
// speedup vs baseline: 3.7375x; 1.7613x over previous
#include <cuda_runtime.h>
#include <cstdint>

// Fused causal linear attention (elu+1), chunked, tf32 mma, persistent state,
// cp.async double-buffered pipeline. [B=8, L=2048, H=16, D=64], chunk C=128.
// One block (256 thr) per (batch,head) pair; 128 blocks.

#define BB 8
#define LL 2048
#define HH 16
#define DD 64
#define MM 64
#define CC 128
#define NC (LL/CC)      // 16
#define NP (BB*HH)      // 128
#define EPSV 1e-6f

// smem layout (floats):
//  buf[2]: Q[128][68], K[128][68], V[128][72]  (raw -> converted in place)
//  Ss[64][72] running state, kc[64] running ksum
#define QK_STR 68
#define V_STR  72
#define OFF_Q  0
#define OFF_K  (128*QK_STR)
#define OFF_V  (2*128*QK_STR)
#define BUF_FLOATS (2*128*QK_STR + 128*V_STR)     // 26624
#define OFF_SS (2*BUF_FLOATS)
#define OFF_KC (OFF_SS + 64*V_STR)
#define SMEM_FLOATS (OFF_KC + 64)                 // 57920
#define SMEM_BYTES  (SMEM_FLOATS * 4)             // 231680 <= 232448

__device__ __forceinline__ float phi(float x) {
    return x > 0.f ? x + 1.f : __expf(x);
}
__device__ __forceinline__ float tf32r(float x) {
    uint32_t u; asm("cvt.rna.tf32.f32 %0, %1;" : "=r"(u) : "f"(x));
    return __uint_as_float(u);
}
#define AS_U(x) __float_as_uint(x)

__device__ __forceinline__ void mma8(float* c, uint32_t a0, uint32_t a1,
                                     uint32_t a2, uint32_t a3,
                                     uint32_t b0, uint32_t b1) {
    asm volatile(
        "mma.sync.aligned.m16n8k8.row.col.f32.tf32.tf32.f32 "
        "{%0,%1,%2,%3}, {%4,%5,%6,%7}, {%8,%9}, {%0,%1,%2,%3};"
        : "+f"(c[0]), "+f"(c[1]), "+f"(c[2]), "+f"(c[3])
        : "r"(a0), "r"(a1), "r"(a2), "r"(a3), "r"(b0), "r"(b1));
}

__device__ __forceinline__ void cp16(uint32_t dst, const float* src) {
    asm volatile("cp.async.ca.shared.global [%0], [%1], 16;"
                 :: "r"(dst), "l"(src) : "memory");
}
#define CP_COMMIT() asm volatile("cp.async.commit_group;" ::: "memory")
#define CP_WAIT1()  asm volatile("cp.async.wait_group 1;" ::: "memory")
#define CP_WAIT0()  asm volatile("cp.async.wait_group 0;" ::: "memory")

// Issue the raw loads for chunk c into buffer buf (each thread: 8 e-slices x 3).
__device__ __forceinline__ void issue_chunk(uint32_t smem_u32, int buf,
                                            size_t base, int tid,
                                            const float* q, const float* k,
                                            const float* v) {
    uint32_t b0 = smem_u32 + (uint32_t)(buf * BUF_FLOATS) * 4;
#pragma unroll
    for (int it = 0; it < 8; it++) {
        int e = tid + it * 256;
        int j = e >> 4, d4 = (e & 15) * 4;
        size_t g = base + (size_t)j * HH * DD + d4;
        cp16(b0 + (OFF_Q + j * QK_STR + d4) * 4, q + g);
        cp16(b0 + (OFF_K + j * QK_STR + d4) * 4, k + g);
        cp16(b0 + (OFF_V + j * V_STR  + d4) * 4, v + g);
    }
    CP_COMMIT();
}

__global__ void __launch_bounds__(256, 1)
fused_lin_attn(const float* __restrict__ qin, const float* __restrict__ kin,
               const float* __restrict__ vin, float* __restrict__ out) {
    extern __shared__ float sm[];
    uint32_t smem_u32 = (uint32_t)__cvta_generic_to_shared(sm);
    float* Ss = sm + OFF_SS;
    float* kc = sm + OFF_KC;

    int p = blockIdx.x;
    int n = p >> 4, h = p & 15;
    int tid = threadIdx.x;
    int w = tid >> 5, lane = tid & 31, gq = lane >> 2, t = lane & 3;
    int m0 = w * 16;
    int ilo = m0 + gq, ihi = ilo + 8;
    const int NT1 = 2 * w + 2;          // triangular tile count for this warp
    int d0 = (w >> 1) * 16;             // KtV tile mapping
    int nb = (w & 1) * 32;
    int srcA = (lane & ~3) | (t >> 1);  // quad shuffle sources for transpose
    int srcB = srcA + 2;
    int sel = t & 1;

    for (int e = tid; e < 64 * V_STR; e += 256) Ss[e] = 0.f;
    if (tid < DD) kc[tid] = 0.f;
    __syncthreads();

    size_t pbase = ((size_t)n * LL * HH + h) * DD;

    // prologue: prefetch chunk 0
    issue_chunk(smem_u32, 0, pbase, tid, qin, kin, vin);

    for (int c = 0; c < NC; c++) {
        int buf = c & 1;
        float* Qs = sm + buf * BUF_FLOATS + OFF_Q;
        float* Ks = sm + buf * BUF_FLOATS + OFF_K;
        float* Vs = sm + buf * BUF_FLOATS + OFF_V;
        size_t base = pbase + (size_t)(c * CC) * HH * DD;

        if (c + 1 < NC) {
            issue_chunk(smem_u32, buf ^ 1,
                        pbase + (size_t)((c + 1) * CC) * HH * DD,
                        tid, qin, kin, vin);
            CP_WAIT1();
        } else {
            CP_WAIT0();
        }

        // ---- convert own slices in place: phi+tf32 on Q,K; tf32 on V ----
#pragma unroll
        for (int it = 0; it < 8; it++) {
            int e = tid + it * 256;
            int j = e >> 4, d4 = (e & 15) * 4;
            float4* qp = (float4*)(Qs + j * QK_STR + d4);
            float4 qv = *qp;
            qv.x = tf32r(phi(qv.x)); qv.y = tf32r(phi(qv.y));
            qv.z = tf32r(phi(qv.z)); qv.w = tf32r(phi(qv.w));
            *qp = qv;
            float4* kp = (float4*)(Ks + j * QK_STR + d4);
            float4 kv = *kp;
            kv.x = tf32r(phi(kv.x)); kv.y = tf32r(phi(kv.y));
            kv.z = tf32r(phi(kv.z)); kv.w = tf32r(phi(kv.w));
            *kp = kv;
            float4* vp = (float4*)(Vs + j * V_STR + d4);
            float4 vv = *vp;
            vv.x = tf32r(vv.x); vv.y = tf32r(vv.y);
            vv.z = tf32r(vv.z); vv.w = tf32r(vv.w);
            *vp = vv;
        }
        __syncthreads();                                   // SYNC1

        // ---- GEMM1: A = phi(Q) phi(K)^T, warp-private rows m0..m0+15 ----
        float acc[16][4];
#pragma unroll
        for (int i = 0; i < 16; i++)
#pragma unroll
            for (int j = 0; j < 4; j++) acc[i][j] = 0.f;

#pragma unroll
        for (int kt = 0; kt < 8; kt++) {
            int k0 = kt * 8;
            uint32_t a0 = AS_U(Qs[ilo * QK_STR + k0 + t]);
            uint32_t a1 = AS_U(Qs[ihi * QK_STR + k0 + t]);
            uint32_t a2 = AS_U(Qs[ilo * QK_STR + k0 + t + 4]);
            uint32_t a3 = AS_U(Qs[ihi * QK_STR + k0 + t + 4]);
#pragma unroll
            for (int nt = 0; nt < 16; nt++) {
                if (nt >= NT1) break;
                int n0 = nt * 8;
                uint32_t b0 = AS_U(Ks[(n0 + gq) * QK_STR + k0 + t]);
                uint32_t b1 = AS_U(Ks[(n0 + gq) * QK_STR + k0 + t + 4]);
                mma8(acc[nt], a0, a1, a2, a3, b0, b1);
            }
        }

        // ---- mask + tf32-round in place + row sums ----
        float rlo = 0.f, rhi = 0.f;
#pragma unroll
        for (int nt = 0; nt < 16; nt++) {
            if (nt >= NT1) break;
            int jc0 = nt * 8 + 2 * t, jc1 = jc0 + 1;
            float c0 = (jc0 <= ilo) ? acc[nt][0] : 0.f;
            float c1 = (jc1 <= ilo) ? acc[nt][1] : 0.f;
            float c2 = (jc0 <= ihi) ? acc[nt][2] : 0.f;
            float c3 = (jc1 <= ihi) ? acc[nt][3] : 0.f;
            rlo += c0 + c1; rhi += c2 + c3;
            acc[nt][0] = tf32r(c0); acc[nt][1] = tf32r(c1);
            acc[nt][2] = tf32r(c2); acc[nt][3] = tf32r(c3);
        }
        // z = rowsum + q.kcum + eps (quad-reduced)
        float qlo = 0.f, qhi = 0.f;
#pragma unroll
        for (int i = 0; i < 16; i++) {
            int d = t * 16 + i;
            float kcd = kc[d];
            qlo += Qs[ilo * QK_STR + d] * kcd;
            qhi += Qs[ihi * QK_STR + d] * kcd;
        }
        rlo += qlo; rhi += qhi;
        rlo += __shfl_xor_sync(0xffffffffu, rlo, 1);
        rlo += __shfl_xor_sync(0xffffffffu, rlo, 2);
        rhi += __shfl_xor_sync(0xffffffffu, rhi, 1);
        rhi += __shfl_xor_sync(0xffffffffu, rhi, 2);
        float izlo = 1.f / (rlo + EPSV);
        float izhi = 1.f / (rhi + EPSV);

        // ---- GEMM2: out = A*V + Qs*S_prev ; A-fragments via quad shuffle ----
        float acc2[8][4];
#pragma unroll
        for (int i = 0; i < 8; i++)
#pragma unroll
            for (int j = 0; j < 4; j++) acc2[i][j] = 0.f;

#pragma unroll
        for (int kt = 0; kt < 16; kt++) {
            if (kt >= NT1) break;
            // transpose D-frag (rows ilo/ihi, cols 2t,2t+1) -> A-frag (cols t,t+4)
            float v00 = __shfl_sync(0xffffffffu, acc[kt][0], srcA);
            float v01 = __shfl_sync(0xffffffffu, acc[kt][1], srcA);
            float v02 = __shfl_sync(0xffffffffu, acc[kt][0], srcB);
            float v03 = __shfl_sync(0xffffffffu, acc[kt][1], srcB);
            uint32_t a0 = AS_U(sel ? v01 : v00);
            uint32_t a2 = AS_U(sel ? v03 : v02);
            float v10 = __shfl_sync(0xffffffffu, acc[kt][2], srcA);
            float v11 = __shfl_sync(0xffffffffu, acc[kt][3], srcA);
            float v12 = __shfl_sync(0xffffffffu, acc[kt][2], srcB);
            float v13 = __shfl_sync(0xffffffffu, acc[kt][3], srcB);
            uint32_t a1 = AS_U(sel ? v11 : v10);
            uint32_t a3 = AS_U(sel ? v13 : v12);
            int k0 = kt * 8;
#pragma unroll
            for (int nt = 0; nt < 8; nt++) {
                int n0 = nt * 8;
                uint32_t b0 = AS_U(Vs[(k0 + t) * V_STR + n0 + gq]);
                uint32_t b1 = AS_U(Vs[(k0 + t + 4) * V_STR + n0 + gq]);
                mma8(acc2[nt], a0, a1, a2, a3, b0, b1);
            }
        }
        if (c > 0) {
#pragma unroll
            for (int kt = 0; kt < 8; kt++) {
                int k0 = kt * 8;
                uint32_t a0 = AS_U(Qs[ilo * QK_STR + k0 + t]);
                uint32_t a1 = AS_U(Qs[ihi * QK_STR + k0 + t]);
                uint32_t a2 = AS_U(Qs[ilo * QK_STR + k0 + t + 4]);
                uint32_t a3 = AS_U(Qs[ihi * QK_STR + k0 + t + 4]);
#pragma unroll
                for (int nt = 0; nt < 8; nt++) {
                    int n0 = nt * 8;
                    uint32_t b0 = AS_U(tf32r(Ss[(k0 + t) * V_STR + n0 + gq]));
                    uint32_t b1 = AS_U(tf32r(Ss[(k0 + t + 4) * V_STR + n0 + gq]));
                    mma8(acc2[nt], a0, a1, a2, a3, b0, b1);
                }
            }
        }

        // ---- GEMM3: KtV partial state (regs) ----
        float acc3[4][4];
#pragma unroll
        for (int i = 0; i < 4; i++)
#pragma unroll
            for (int j = 0; j < 4; j++) acc3[i][j] = 0.f;
#pragma unroll
        for (int kt = 0; kt < 16; kt++) {
            int k0 = kt * 8;
            uint32_t a0 = AS_U(Ks[(k0 + t) * QK_STR + d0 + gq]);
            uint32_t a1 = AS_U(Ks[(k0 + t) * QK_STR + d0 + gq + 8]);
            uint32_t a2 = AS_U(Ks[(k0 + t + 4) * QK_STR + d0 + gq]);
            uint32_t a3 = AS_U(Ks[(k0 + t + 4) * QK_STR + d0 + gq + 8]);
#pragma unroll
            for (int nt = 0; nt < 4; nt++) {
                int n0 = nb + nt * 8;
                uint32_t b0 = AS_U(Vs[(k0 + t) * V_STR + n0 + gq]);
                uint32_t b1 = AS_U(Vs[(k0 + t + 4) * V_STR + n0 + gq]);
                mma8(acc3[nt], a0, a1, a2, a3, b0, b1);
            }
        }
        float ksum = 0.f;
        if (tid < DD) {
#pragma unroll 8
            for (int j = 0; j < CC; j++) ksum += Ks[j * QK_STR + tid];
        }
        __syncthreads();                                   // S2

        // ---- state update ----
#pragma unroll
        for (int nt = 0; nt < 4; nt++) {
            int n0 = nb + nt * 8 + 2 * t;
            float2* s0 = (float2*)(Ss + (d0 + gq) * V_STR + n0);
            float2* s1 = (float2*)(Ss + (d0 + gq + 8) * V_STR + n0);
            float2 v0 = *s0, v1 = *s1;
            v0.x += acc3[nt][0]; v0.y += acc3[nt][1];
            v1.x += acc3[nt][2]; v1.y += acc3[nt][3];
            *s0 = v0; *s1 = v1;
        }
        if (tid < DD) kc[tid] += ksum;

        // ---- epilogue: direct STG.64 (each quad writes full 32B sectors) ----
        float* orow_lo = out + base + (size_t)ilo * HH * DD;
        float* orow_hi = out + base + (size_t)ihi * HH * DD;
#pragma unroll
        for (int nt = 0; nt < 8; nt++) {
            int n0 = nt * 8 + 2 * t;
            *(float2*)(orow_lo + n0) =
                make_float2(acc2[nt][0] * izlo, acc2[nt][1] * izlo);
            *(float2*)(orow_hi + n0) =
                make_float2(acc2[nt][2] * izhi, acc2[nt][3] * izhi);
        }
    }
}

// ---------------------------------------------------------------------------

extern "C" void kernel_launch(void* const* d_in, const int* in_sizes, int n_in,
                              void* d_out, int out_size) {
    const float* q = (const float*)d_in[0];
    const float* k = (const float*)d_in[1];
    const float* v = (const float*)d_in[2];
    float* out = (float*)d_out;

    cudaFuncSetAttribute(fused_lin_attn,
                         cudaFuncAttributeMaxDynamicSharedMemorySize, SMEM_BYTES);
    fused_lin_attn<<<NP, 256, SMEM_BYTES>>>(q, k, v, out);
}